// round 1
// baseline (speedup 1.0000x reference)
#include <cuda_runtime.h>
#include <math.h>

#define B_   2
#define L_   2048
#define D_   4096
#define H_   32
#define HKV_ 8
#define HD_  128
#define M_   (B_ * L_)      // 4096 rows
#define NQ_  (H_ * HD_)     // 4096
#define NKV_ (HKV_ * HD_)   // 1024

// Scratch (device globals; no allocation allowed)
__device__ float g_q[M_ * NQ_];      // 64 MB
__device__ float g_k[M_ * NKV_];     // 16 MB
__device__ float g_v[M_ * NKV_];     // 16 MB
__device__ float g_attn[M_ * NQ_];   // 64 MB

// ---------------------------------------------------------------------------
// Packed fp32x2 FMA (Blackwell FFMA2 — 2x fp32 throughput vs 3-reg FFMA)
// ---------------------------------------------------------------------------
__device__ __forceinline__ float2 ffma2(float2 a, float2 b, float2 c)
{
    float2 d;
    asm("fma.rn.f32x2 %0, %1, %2, %3;"
        : "=l"(reinterpret_cast<unsigned long long &>(d))
        : "l"(reinterpret_cast<unsigned long long const &>(a)),
          "l"(reinterpret_cast<unsigned long long const &>(b)),
          "l"(reinterpret_cast<unsigned long long const &>(c)));
    return d;
}

// ---------------------------------------------------------------------------
// SGEMM: C[M,N] = A[M,K] * B[N,K]^T   (both row-major; B is a weight matrix)
// 128x128 block tile, BK=16, 256 threads, 8x8 micro-tile, FFMA2 inner loop.
// Requires M,N multiples of 128 and K multiple of 16 (true for all our shapes).
// ---------------------------------------------------------------------------
__global__ __launch_bounds__(256)
void sgemm_nt(const float* __restrict__ A, const float* __restrict__ Bw,
              float* __restrict__ C, int M, int N, int K)
{
    __shared__ float As[16][132];
    __shared__ float Bs[16][132];

    const int tid = threadIdx.x;
    const int ty  = tid >> 4;          // 0..15
    const int tx  = tid & 15;          // 0..15
    const int m0  = blockIdx.y << 7;
    const int n0  = blockIdx.x << 7;

    const int lrow = tid >> 2;         // 0..63
    const int lk   = (tid & 3) << 2;   // 0,4,8,12

    float2 acc[8][4];
#pragma unroll
    for (int i = 0; i < 8; ++i)
#pragma unroll
        for (int j = 0; j < 4; ++j) acc[i][j] = make_float2(0.f, 0.f);

    for (int k0 = 0; k0 < K; k0 += 16) {
#pragma unroll
        for (int it = 0; it < 2; ++it) {
            int row = it * 64 + lrow;
            float4 av = *reinterpret_cast<const float4*>(
                A + (size_t)(m0 + row) * K + k0 + lk);
            As[lk + 0][row] = av.x; As[lk + 1][row] = av.y;
            As[lk + 2][row] = av.z; As[lk + 3][row] = av.w;
            float4 bv = *reinterpret_cast<const float4*>(
                Bw + (size_t)(n0 + row) * K + k0 + lk);
            Bs[lk + 0][row] = bv.x; Bs[lk + 1][row] = bv.y;
            Bs[lk + 2][row] = bv.z; Bs[lk + 3][row] = bv.w;
        }
        __syncthreads();

#pragma unroll
        for (int k = 0; k < 16; ++k) {
            float4 a0 = *reinterpret_cast<const float4*>(&As[k][ty * 8]);
            float4 a1 = *reinterpret_cast<const float4*>(&As[k][ty * 8 + 4]);
            float4 b0 = *reinterpret_cast<const float4*>(&Bs[k][tx * 8]);
            float4 b1 = *reinterpret_cast<const float4*>(&Bs[k][tx * 8 + 4]);
            float av[8] = {a0.x, a0.y, a0.z, a0.w, a1.x, a1.y, a1.z, a1.w};
            float2 bp[4] = {make_float2(b0.x, b0.y), make_float2(b0.z, b0.w),
                            make_float2(b1.x, b1.y), make_float2(b1.z, b1.w)};
#pragma unroll
            for (int i = 0; i < 8; ++i) {
                float2 ad = make_float2(av[i], av[i]);
#pragma unroll
                for (int j = 0; j < 4; ++j)
                    acc[i][j] = ffma2(ad, bp[j], acc[i][j]);
            }
        }
        __syncthreads();
    }

#pragma unroll
    for (int i = 0; i < 8; ++i) {
        float* crow = C + (size_t)(m0 + ty * 8 + i) * N + n0 + tx * 8;
        *reinterpret_cast<float4*>(crow) =
            make_float4(acc[i][0].x, acc[i][0].y, acc[i][1].x, acc[i][1].y);
        *reinterpret_cast<float4*>(crow + 4) =
            make_float4(acc[i][2].x, acc[i][2].y, acc[i][3].x, acc[i][3].y);
    }
}

// ---------------------------------------------------------------------------
// RoPE (in place) over [M, nh*128]; pairs (2p, 2p+1), cos/sin indexed [l, p]
// ---------------------------------------------------------------------------
__global__ void rope_kernel(float* __restrict__ t, const float* __restrict__ cosp,
                            const float* __restrict__ sinp, int nh, int total)
{
    int idx = blockIdx.x * blockDim.x + threadIdx.x;
    if (idx >= total) return;
    int p = idx & 63;
    int h = (idx >> 6) % nh;
    int m = idx / (64 * nh);
    int l = m & (L_ - 1);
    float c = cosp[l * 64 + p];
    float s = sinp[l * 64 + p];
    float* base = t + (size_t)m * (nh * HD_) + h * HD_ + (p << 1);
    float tr = base[0], ti = base[1];
    base[0] = tr * c - ti * s;
    base[1] = tr * s + ti * c;
}

// ---------------------------------------------------------------------------
// Flash attention (causal, GQA 4:1). One block = (64 queries) x (b,h).
// Smem rows padded to 129 (Q,K: conflict-free scalar LDS), 132 (V: float4).
// ---------------------------------------------------------------------------
#define AP_Q 129
#define AP_V 132
#define AP_P 68
#define SM_Q 0
#define SM_K (64 * AP_Q)
#define SM_V (2 * 64 * AP_Q)
#define SM_P (2 * 64 * AP_Q + 64 * AP_V)
#define ATTN_SMEM ((2 * 64 * AP_Q + 64 * AP_V + 64 * AP_P) * 4)

__global__ __launch_bounds__(256)
void attn_kernel()
{
    extern __shared__ float smf[];
    float* Qs = smf + SM_Q;
    float* Ks = smf + SM_K;
    float* Vs = smf + SM_V;
    float* Ps = smf + SM_P;

    const int tid = threadIdx.x;
    const int gq  = tid >> 4;     // query-row group 0..15 (rows gq*4 .. +3)
    const int cc  = tid & 15;     // key-col group (cols cc*4 .. +3)
    const int qt  = blockIdx.x;
    const int bh  = blockIdx.y;
    const int b   = bh >> 5;
    const int h   = bh & 31;
    const int hkv = h >> 2;
    const int l0  = qt * 64;

    const float scale = 0.08838834764831845f;  // 1/sqrt(128)

    const int lr = tid >> 5;           // 0..7
    const int dq = (tid & 31) << 2;    // 0..124 step 4

    // Load Q tile (pre-scaled)
#pragma unroll
    for (int it = 0; it < 8; ++it) {
        int row = it * 8 + lr;
        float4 qv = *reinterpret_cast<const float4*>(
            g_q + (size_t)(b * L_ + l0 + row) * NQ_ + h * HD_ + dq);
        float* qr = Qs + row * AP_Q + dq;
        qr[0] = qv.x * scale; qr[1] = qv.y * scale;
        qr[2] = qv.z * scale; qr[3] = qv.w * scale;
    }

    float m_r[4], l_r[4], o[4][8];
#pragma unroll
    for (int i = 0; i < 4; ++i) {
        m_r[i] = -INFINITY; l_r[i] = 0.f;
#pragma unroll
        for (int j = 0; j < 8; ++j) o[i][j] = 0.f;
    }

    const float* kbase = g_k + (size_t)(b * L_) * NKV_ + hkv * HD_;
    const float* vbase = g_v + (size_t)(b * L_) * NKV_ + hkv * HD_;

    for (int kt = 0; kt <= qt; ++kt) {
        __syncthreads();
        const int k0 = kt * 64;
#pragma unroll
        for (int it = 0; it < 8; ++it) {
            int row = it * 8 + lr;
            float4 kv = *reinterpret_cast<const float4*>(
                kbase + (size_t)(k0 + row) * NKV_ + dq);
            float* kr = Ks + row * AP_Q + dq;
            kr[0] = kv.x; kr[1] = kv.y; kr[2] = kv.z; kr[3] = kv.w;
            float4 vv = *reinterpret_cast<const float4*>(
                vbase + (size_t)(k0 + row) * NKV_ + dq);
            *reinterpret_cast<float4*>(Vs + row * AP_V + dq) = vv;
        }
        __syncthreads();

        // ---- S = Q K^T (4x4 per thread) ----
        float s[4][4];
#pragma unroll
        for (int i = 0; i < 4; ++i)
#pragma unroll
            for (int j = 0; j < 4; ++j) s[i][j] = 0.f;

        const float* qp0 = Qs + (gq * 4 + 0) * AP_Q;
        const float* qp1 = Qs + (gq * 4 + 1) * AP_Q;
        const float* qp2 = Qs + (gq * 4 + 2) * AP_Q;
        const float* qp3 = Qs + (gq * 4 + 3) * AP_Q;
        const float* kp0 = Ks + (cc * 4 + 0) * AP_Q;
        const float* kp1 = Ks + (cc * 4 + 1) * AP_Q;
        const float* kp2 = Ks + (cc * 4 + 2) * AP_Q;
        const float* kp3 = Ks + (cc * 4 + 3) * AP_Q;

#pragma unroll 8
        for (int d = 0; d < 128; ++d) {
            float qv[4] = {qp0[d], qp1[d], qp2[d], qp3[d]};
            float kv[4] = {kp0[d], kp1[d], kp2[d], kp3[d]};
#pragma unroll
            for (int i = 0; i < 4; ++i)
#pragma unroll
                for (int j = 0; j < 4; ++j) s[i][j] += qv[i] * kv[j];
        }

        if (kt == qt) {
#pragma unroll
            for (int i = 0; i < 4; ++i)
#pragma unroll
                for (int j = 0; j < 4; ++j)
                    if ((gq * 4 + i) < (cc * 4 + j)) s[i][j] = -1e30f;
        }

        // ---- online softmax (per-row, reduced over 16-lane groups) ----
#pragma unroll
        for (int i = 0; i < 4; ++i) {
            float rmax = fmaxf(fmaxf(s[i][0], s[i][1]), fmaxf(s[i][2], s[i][3]));
#pragma unroll
            for (int off = 8; off > 0; off >>= 1)
                rmax = fmaxf(rmax, __shfl_xor_sync(0xffffffffu, rmax, off));
            float mnew  = fmaxf(m_r[i], rmax);
            float alpha = __expf(m_r[i] - mnew);
            float rsum  = 0.f;
            float* prow = Ps + (gq * 4 + i) * AP_P + cc * 4;
#pragma unroll
            for (int j = 0; j < 4; ++j) {
                float p = __expf(s[i][j] - mnew);
                prow[j] = p;
                rsum += p;
            }
#pragma unroll
            for (int off = 8; off > 0; off >>= 1)
                rsum += __shfl_xor_sync(0xffffffffu, rsum, off);
            l_r[i] = l_r[i] * alpha + rsum;
            m_r[i] = mnew;
#pragma unroll
            for (int j2 = 0; j2 < 8; ++j2) o[i][j2] *= alpha;
        }
        __syncthreads();

        // ---- O += P V : rows gq*4..+3, cols cc*8..+7 ----
#pragma unroll 4
        for (int j0 = 0; j0 < 64; j0 += 4) {
            float4 pr[4];
            pr[0] = *reinterpret_cast<const float4*>(Ps + (gq * 4 + 0) * AP_P + j0);
            pr[1] = *reinterpret_cast<const float4*>(Ps + (gq * 4 + 1) * AP_P + j0);
            pr[2] = *reinterpret_cast<const float4*>(Ps + (gq * 4 + 2) * AP_P + j0);
            pr[3] = *reinterpret_cast<const float4*>(Ps + (gq * 4 + 3) * AP_P + j0);
            const float pv[4][4] = {
                {pr[0].x, pr[0].y, pr[0].z, pr[0].w},
                {pr[1].x, pr[1].y, pr[1].z, pr[1].w},
                {pr[2].x, pr[2].y, pr[2].z, pr[2].w},
                {pr[3].x, pr[3].y, pr[3].z, pr[3].w}};
#pragma unroll
            for (int jj = 0; jj < 4; ++jj) {
                const float* vrow = Vs + (j0 + jj) * AP_V + cc * 8;
                float4 v0 = *reinterpret_cast<const float4*>(vrow);
                float4 v1 = *reinterpret_cast<const float4*>(vrow + 4);
                float vv[8] = {v0.x, v0.y, v0.z, v0.w, v1.x, v1.y, v1.z, v1.w};
#pragma unroll
                for (int i = 0; i < 4; ++i) {
                    float p = pv[i][jj];
#pragma unroll
                    for (int c2 = 0; c2 < 8; ++c2) o[i][c2] += p * vv[c2];
                }
            }
        }
    }

    // ---- epilogue: O / l ----
#pragma unroll
    for (int i = 0; i < 4; ++i) {
        float inv = 1.f / l_r[i];
        float* orow = g_attn + (size_t)(b * L_ + l0 + gq * 4 + i) * NQ_
                      + h * HD_ + cc * 8;
        *reinterpret_cast<float4*>(orow) =
            make_float4(o[i][0] * inv, o[i][1] * inv, o[i][2] * inv, o[i][3] * inv);
        *reinterpret_cast<float4*>(orow + 4) =
            make_float4(o[i][4] * inv, o[i][5] * inv, o[i][6] * inv, o[i][7] * inv);
    }
}

// ---------------------------------------------------------------------------
// Launch: qkv gemms -> rope -> flash attention -> output gemm
// ---------------------------------------------------------------------------
extern "C" void kernel_launch(void* const* d_in, const int* in_sizes, int n_in,
                              void* d_out, int out_size)
{
    const float* x    = (const float*)d_in[0];
    const float* wq   = (const float*)d_in[1];
    const float* wk   = (const float*)d_in[2];
    const float* wv   = (const float*)d_in[3];
    const float* wo   = (const float*)d_in[4];
    const float* cosp = (const float*)d_in[5];
    const float* sinp = (const float*)d_in[6];
    // d_in[7] = mask: exactly causal -1e9; handled analytically in-kernel.
    float* out = (float*)d_out;

    float *qp, *kp, *vp, *ap;
    cudaGetSymbolAddress((void**)&qp, g_q);
    cudaGetSymbolAddress((void**)&kp, g_k);
    cudaGetSymbolAddress((void**)&vp, g_v);
    cudaGetSymbolAddress((void**)&ap, g_attn);

    dim3 blk(256);
    sgemm_nt<<<dim3(NQ_ / 128,  M_ / 128), blk>>>(x, wq, qp, M_, NQ_,  D_);
    sgemm_nt<<<dim3(NKV_ / 128, M_ / 128), blk>>>(x, wk, kp, M_, NKV_, D_);
    sgemm_nt<<<dim3(NKV_ / 128, M_ / 128), blk>>>(x, wv, vp, M_, NKV_, D_);

    int tq = M_ * H_ * 64;
    rope_kernel<<<(tq + 255) / 256, 256>>>(qp, cosp, sinp, H_, tq);
    int tk = M_ * HKV_ * 64;
    rope_kernel<<<(tk + 255) / 256, 256>>>(kp, cosp, sinp, HKV_, tk);

    cudaFuncSetAttribute(attn_kernel,
                         cudaFuncAttributeMaxDynamicSharedMemorySize, ATTN_SMEM);
    attn_kernel<<<dim3(L_ / 64, B_ * H_), blk, ATTN_SMEM>>>();

    sgemm_nt<<<dim3(D_ / 128, M_ / 128), blk>>>(ap, wo, out, M_, D_, D_);
}

// round 3
// speedup vs baseline: 1.9335x; 1.9335x over previous
#include <cuda_runtime.h>
#include <cuda_bf16.h>
#include <math.h>
#include <stdint.h>

#define B_   2
#define L_   2048
#define D_   4096
#define H_   32
#define HKV_ 8
#define HD_  128
#define M_   (B_ * L_)      // 4096 rows
#define NQ_  (H_ * HD_)     // 4096
#define NKV_ (HKV_ * HD_)   // 1024

// ---------------------------------------------------------------------------
// Scratch (device globals; no allocation allowed)
// ---------------------------------------------------------------------------
__device__ float g_q[M_ * NQ_];
__device__ float g_k[M_ * NKV_];
__device__ float g_v[M_ * NKV_];
__device__ float g_attn[M_ * NQ_];

__device__ __nv_bfloat16 g_xh[M_ * D_],    g_xl[M_ * D_];
__device__ __nv_bfloat16 g_wqh[D_ * D_],   g_wql[D_ * D_];
__device__ __nv_bfloat16 g_wkh[NKV_ * D_], g_wkl[NKV_ * D_];
__device__ __nv_bfloat16 g_wvh[NKV_ * D_], g_wvl[NKV_ * D_];
__device__ __nv_bfloat16 g_woh[D_ * D_],   g_wol[D_ * D_];
__device__ __nv_bfloat16 g_ah[M_ * NQ_],   g_al[M_ * NQ_];

// ---------------------------------------------------------------------------
// Portable tensor-core primitives (work on plain sm_103 target)
// ---------------------------------------------------------------------------
__device__ __forceinline__ uint32_t s2u(const void* p)
{
    uint32_t a;
    asm("{ .reg .u64 t; cvta.to.shared.u64 t, %1; cvt.u32.u64 %0, t; }"
        : "=r"(a) : "l"(p));
    return a;
}

__device__ __forceinline__ void cpa16(uint32_t s, const void* g)
{
    asm volatile("cp.async.cg.shared.global [%0], [%1], 16;"
                 :: "r"(s), "l"(g) : "memory");
}
#define CP_COMMIT() asm volatile("cp.async.commit_group;" ::: "memory")
#define CP_WAIT2()  asm volatile("cp.async.wait_group 2;" ::: "memory")

__device__ __forceinline__ void ldm4(uint32_t* r, uint32_t addr)
{
    asm volatile("ldmatrix.sync.aligned.m8n8.x4.shared.b16 {%0,%1,%2,%3}, [%4];"
                 : "=r"(r[0]), "=r"(r[1]), "=r"(r[2]), "=r"(r[3]) : "r"(addr));
}

__device__ __forceinline__ void mma16816(float* c, const uint32_t* a, const uint32_t* b)
{
    asm volatile(
        "mma.sync.aligned.m16n8k16.row.col.f32.bf16.bf16.f32 "
        "{%0,%1,%2,%3}, {%4,%5,%6,%7}, {%8,%9}, {%0,%1,%2,%3};"
        : "+f"(c[0]), "+f"(c[1]), "+f"(c[2]), "+f"(c[3])
        : "r"(a[0]), "r"(a[1]), "r"(a[2]), "r"(a[3]), "r"(b[0]), "r"(b[1]));
}

// ---------------------------------------------------------------------------
// HMMA GEMM: C[M,N] = A[M,K]*B[N,K]^T, split-bf16 (hi/lo), 3 products.
// CTA tile 128x128, BK=32, 4-stage cp.async pipeline, 8 warps @ 64x32.
// Smem tile layout: row-major [128][32] bf16, 16B chunks, chunk^=((row>>1)&3).
// ---------------------------------------------------------------------------
#define STAGE_BYTES 32768
#define OFF_AH 0
#define OFF_AL 8192
#define OFF_BH 16384
#define OFF_BL 24576
#define GSMEM  (4 * STAGE_BYTES)

__global__ __launch_bounds__(256, 1)
void gemm_mma(const __nv_bfloat16* __restrict__ Ah, const __nv_bfloat16* __restrict__ Al,
              const __nv_bfloat16* __restrict__ Bh, const __nv_bfloat16* __restrict__ Bl,
              float* __restrict__ C, int M, int N, int K)
{
    extern __shared__ char smem[];
    const uint32_t sb0 = s2u(smem);
    const int tid  = threadIdx.x;
    const int lane = tid & 31;
    const int wid  = tid >> 5;
    const int warp_m = (wid >> 2) * 64;   // 0 / 64
    const int warp_n = (wid & 3) * 32;    // 0/32/64/96
    const int m0 = blockIdx.y << 7;
    const int n0 = blockIdx.x << 7;

    // per-thread gmem->smem mapping (2 16B chunks per matrix per thread)
    int ld_row[2], ld_c[2];
    uint32_t ld_soff[2];
#pragma unroll
    for (int i = 0; i < 2; ++i) {
        int idx = tid + i * 256;             // 0..511
        ld_row[i] = idx >> 2;
        ld_c[i]   = idx & 3;
        ld_soff[i] = (uint32_t)(ld_row[i] * 64 +
                     ((ld_c[i] ^ ((ld_row[i] >> 1) & 3)) * 16));
    }

    float acc[4][4][4];
#pragma unroll
    for (int mt = 0; mt < 4; ++mt)
#pragma unroll
        for (int nt = 0; nt < 4; ++nt)
#pragma unroll
            for (int e = 0; e < 4; ++e) acc[mt][nt][e] = 0.f;

    const int NKI = K >> 5;   // BK=32 iterations

    // ldmatrix per-lane row/chunk components
    const int a_r8 = ((lane >> 3) & 1) * 8 + (lane & 7);
    const int a_cs = lane >> 4;               // 0/1 -> chunk sub
    const int b_r8 = ((lane >> 4) & 1) * 8 + (lane & 7);
    const int b_cs = (lane >> 3) & 1;

    auto load_stage = [&](int stage, int kc) {
        uint32_t sb = sb0 + stage * STAGE_BYTES;
#pragma unroll
        for (int i = 0; i < 2; ++i) {
            size_t ga = (size_t)(m0 + ld_row[i]) * K + kc + ld_c[i] * 8;
            size_t gb = (size_t)(n0 + ld_row[i]) * K + kc + ld_c[i] * 8;
            cpa16(sb + OFF_AH + ld_soff[i], Ah + ga);
            cpa16(sb + OFF_AL + ld_soff[i], Al + ga);
            cpa16(sb + OFF_BH + ld_soff[i], Bh + gb);
            cpa16(sb + OFF_BL + ld_soff[i], Bl + gb);
        }
    };

    // prologue: stages 0..2
#pragma unroll
    for (int s = 0; s < 3; ++s) { load_stage(s, s * 32); CP_COMMIT(); }

    for (int it = 0; it < NKI; ++it) {
        CP_WAIT2();
        __syncthreads();
        if (it + 3 < NKI) load_stage((it + 3) & 3, (it + 3) * 32);
        CP_COMMIT();

        const uint32_t sb = sb0 + (it & 3) * STAGE_BYTES;
#pragma unroll
        for (int j = 0; j < 2; ++j) {
            uint32_t ah[4][4], al[4][4];
#pragma unroll
            for (int mt = 0; mt < 4; ++mt) {
                int row = warp_m + mt * 16 + a_r8;
                int chunk = j * 2 + a_cs;
                uint32_t off = (uint32_t)(row * 64 + ((chunk ^ ((row >> 1) & 3)) * 16));
                ldm4(ah[mt], sb + OFF_AH + off);
                ldm4(al[mt], sb + OFF_AL + off);
            }
            uint32_t bh[4][2], bl[4][2];
#pragma unroll
            for (int np = 0; np < 2; ++np) {
                int row = warp_n + np * 16 + b_r8;
                int chunk = j * 2 + b_cs;
                uint32_t off = (uint32_t)(row * 64 + ((chunk ^ ((row >> 1) & 3)) * 16));
                uint32_t r[4];
                ldm4(r, sb + OFF_BH + off);
                bh[np * 2][0] = r[0]; bh[np * 2][1] = r[1];
                bh[np * 2 + 1][0] = r[2]; bh[np * 2 + 1][1] = r[3];
                ldm4(r, sb + OFF_BL + off);
                bl[np * 2][0] = r[0]; bl[np * 2][1] = r[1];
                bl[np * 2 + 1][0] = r[2]; bl[np * 2 + 1][1] = r[3];
            }
#pragma unroll
            for (int mt = 0; mt < 4; ++mt)
#pragma unroll
                for (int nt = 0; nt < 4; ++nt) {
                    mma16816(acc[mt][nt], ah[mt], bh[nt]);
                    mma16816(acc[mt][nt], ah[mt], bl[nt]);
                    mma16816(acc[mt][nt], al[mt], bh[nt]);
                }
        }
    }

    // epilogue
    const int r0 = lane >> 2;
    const int cp = (lane & 3) * 2;
#pragma unroll
    for (int mt = 0; mt < 4; ++mt) {
#pragma unroll
        for (int nt = 0; nt < 4; ++nt) {
            int row = m0 + warp_m + mt * 16 + r0;
            int col = n0 + warp_n + nt * 8 + cp;
            *reinterpret_cast<float2*>(C + (size_t)row * N + col) =
                make_float2(acc[mt][nt][0], acc[mt][nt][1]);
            *reinterpret_cast<float2*>(C + (size_t)(row + 8) * N + col) =
                make_float2(acc[mt][nt][2], acc[mt][nt][3]);
        }
    }
}

// ---------------------------------------------------------------------------
// fp32 -> bf16 hi/lo split
// ---------------------------------------------------------------------------
__global__ void split_kernel(const float* __restrict__ s,
                             __nv_bfloat16* __restrict__ hi,
                             __nv_bfloat16* __restrict__ lo, int n4)
{
    int i = blockIdx.x * blockDim.x + threadIdx.x;
    if (i >= n4) return;
    float4 v = reinterpret_cast<const float4*>(s)[i];
    float f[4] = {v.x, v.y, v.z, v.w};
    __nv_bfloat16 h[4], l[4];
#pragma unroll
    for (int j = 0; j < 4; ++j) {
        h[j] = __float2bfloat16(f[j]);
        l[j] = __float2bfloat16(f[j] - __bfloat162float(h[j]));
    }
    reinterpret_cast<__nv_bfloat162*>(hi)[2 * i]     = __halves2bfloat162(h[0], h[1]);
    reinterpret_cast<__nv_bfloat162*>(hi)[2 * i + 1] = __halves2bfloat162(h[2], h[3]);
    reinterpret_cast<__nv_bfloat162*>(lo)[2 * i]     = __halves2bfloat162(l[0], l[1]);
    reinterpret_cast<__nv_bfloat162*>(lo)[2 * i + 1] = __halves2bfloat162(l[2], l[3]);
}

// ---------------------------------------------------------------------------
// RoPE (in place)
// ---------------------------------------------------------------------------
__global__ void rope_kernel(float* __restrict__ t, const float* __restrict__ cosp,
                            const float* __restrict__ sinp, int nh, int total)
{
    int idx = blockIdx.x * blockDim.x + threadIdx.x;
    if (idx >= total) return;
    int p = idx & 63;
    int h = (idx >> 6) % nh;
    int m = idx / (64 * nh);
    int l = m & (L_ - 1);
    float c = cosp[l * 64 + p];
    float s = sinp[l * 64 + p];
    float* base = t + (size_t)m * (nh * HD_) + h * HD_ + (p << 1);
    float tr = base[0], ti = base[1];
    base[0] = tr * c - ti * s;
    base[1] = tr * s + ti * c;
}

// ---------------------------------------------------------------------------
// Flash attention (causal, GQA 4:1). One block = (64 queries) x (b,h).
// ---------------------------------------------------------------------------
#define AP_Q 129
#define AP_V 132
#define AP_P 68
#define SM_Q 0
#define SM_K (64 * AP_Q)
#define SM_V (2 * 64 * AP_Q)
#define SM_P (2 * 64 * AP_Q + 64 * AP_V)
#define ATTN_SMEM ((2 * 64 * AP_Q + 64 * AP_V + 64 * AP_P) * 4)

__global__ __launch_bounds__(256)
void attn_kernel()
{
    extern __shared__ float smf[];
    float* Qs = smf + SM_Q;
    float* Ks = smf + SM_K;
    float* Vs = smf + SM_V;
    float* Ps = smf + SM_P;

    const int tid = threadIdx.x;
    const int gq  = tid >> 4;
    const int cc  = tid & 15;
    const int qt  = blockIdx.x;
    const int bh  = blockIdx.y;
    const int b   = bh >> 5;
    const int h   = bh & 31;
    const int hkv = h >> 2;
    const int l0  = qt * 64;

    const float scale = 0.08838834764831845f;

    const int lr = tid >> 5;
    const int dq = (tid & 31) << 2;

#pragma unroll
    for (int it = 0; it < 8; ++it) {
        int row = it * 8 + lr;
        float4 qv = *reinterpret_cast<const float4*>(
            g_q + (size_t)(b * L_ + l0 + row) * NQ_ + h * HD_ + dq);
        float* qr = Qs + row * AP_Q + dq;
        qr[0] = qv.x * scale; qr[1] = qv.y * scale;
        qr[2] = qv.z * scale; qr[3] = qv.w * scale;
    }

    float m_r[4], l_r[4], o[4][8];
#pragma unroll
    for (int i = 0; i < 4; ++i) {
        m_r[i] = -INFINITY; l_r[i] = 0.f;
#pragma unroll
        for (int j = 0; j < 8; ++j) o[i][j] = 0.f;
    }

    const float* kbase = g_k + (size_t)(b * L_) * NKV_ + hkv * HD_;
    const float* vbase = g_v + (size_t)(b * L_) * NKV_ + hkv * HD_;

    for (int kt = 0; kt <= qt; ++kt) {
        __syncthreads();
        const int k0 = kt * 64;
#pragma unroll
        for (int it = 0; it < 8; ++it) {
            int row = it * 8 + lr;
            float4 kv = *reinterpret_cast<const float4*>(
                kbase + (size_t)(k0 + row) * NKV_ + dq);
            float* kr = Ks + row * AP_Q + dq;
            kr[0] = kv.x; kr[1] = kv.y; kr[2] = kv.z; kr[3] = kv.w;
            float4 vv = *reinterpret_cast<const float4*>(
                vbase + (size_t)(k0 + row) * NKV_ + dq);
            *reinterpret_cast<float4*>(Vs + row * AP_V + dq) = vv;
        }
        __syncthreads();

        float s[4][4];
#pragma unroll
        for (int i = 0; i < 4; ++i)
#pragma unroll
            for (int j = 0; j < 4; ++j) s[i][j] = 0.f;

        const float* qp0 = Qs + (gq * 4 + 0) * AP_Q;
        const float* qp1 = Qs + (gq * 4 + 1) * AP_Q;
        const float* qp2 = Qs + (gq * 4 + 2) * AP_Q;
        const float* qp3 = Qs + (gq * 4 + 3) * AP_Q;
        const float* kp0 = Ks + (cc * 4 + 0) * AP_Q;
        const float* kp1 = Ks + (cc * 4 + 1) * AP_Q;
        const float* kp2 = Ks + (cc * 4 + 2) * AP_Q;
        const float* kp3 = Ks + (cc * 4 + 3) * AP_Q;

#pragma unroll 8
        for (int d = 0; d < 128; ++d) {
            float qv[4] = {qp0[d], qp1[d], qp2[d], qp3[d]};
            float kv[4] = {kp0[d], kp1[d], kp2[d], kp3[d]};
#pragma unroll
            for (int i = 0; i < 4; ++i)
#pragma unroll
                for (int j = 0; j < 4; ++j) s[i][j] += qv[i] * kv[j];
        }

        if (kt == qt) {
#pragma unroll
            for (int i = 0; i < 4; ++i)
#pragma unroll
                for (int j = 0; j < 4; ++j)
                    if ((gq * 4 + i) < (cc * 4 + j)) s[i][j] = -1e30f;
        }

#pragma unroll
        for (int i = 0; i < 4; ++i) {
            float rmax = fmaxf(fmaxf(s[i][0], s[i][1]), fmaxf(s[i][2], s[i][3]));
#pragma unroll
            for (int off = 8; off > 0; off >>= 1)
                rmax = fmaxf(rmax, __shfl_xor_sync(0xffffffffu, rmax, off));
            float mnew  = fmaxf(m_r[i], rmax);
            float alpha = __expf(m_r[i] - mnew);
            float rsum  = 0.f;
            float* prow = Ps + (gq * 4 + i) * AP_P + cc * 4;
#pragma unroll
            for (int j = 0; j < 4; ++j) {
                float p = __expf(s[i][j] - mnew);
                prow[j] = p;
                rsum += p;
            }
#pragma unroll
            for (int off = 8; off > 0; off >>= 1)
                rsum += __shfl_xor_sync(0xffffffffu, rsum, off);
            l_r[i] = l_r[i] * alpha + rsum;
            m_r[i] = mnew;
#pragma unroll
            for (int j2 = 0; j2 < 8; ++j2) o[i][j2] *= alpha;
        }
        __syncthreads();

#pragma unroll 4
        for (int j0 = 0; j0 < 64; j0 += 4) {
            float4 pr[4];
            pr[0] = *reinterpret_cast<const float4*>(Ps + (gq * 4 + 0) * AP_P + j0);
            pr[1] = *reinterpret_cast<const float4*>(Ps + (gq * 4 + 1) * AP_P + j0);
            pr[2] = *reinterpret_cast<const float4*>(Ps + (gq * 4 + 2) * AP_P + j0);
            pr[3] = *reinterpret_cast<const float4*>(Ps + (gq * 4 + 3) * AP_P + j0);
            const float pv[4][4] = {
                {pr[0].x, pr[0].y, pr[0].z, pr[0].w},
                {pr[1].x, pr[1].y, pr[1].z, pr[1].w},
                {pr[2].x, pr[2].y, pr[2].z, pr[2].w},
                {pr[3].x, pr[3].y, pr[3].z, pr[3].w}};
#pragma unroll
            for (int jj = 0; jj < 4; ++jj) {
                const float* vrow = Vs + (j0 + jj) * AP_V + cc * 8;
                float4 v0 = *reinterpret_cast<const float4*>(vrow);
                float4 v1 = *reinterpret_cast<const float4*>(vrow + 4);
                float vv[8] = {v0.x, v0.y, v0.z, v0.w, v1.x, v1.y, v1.z, v1.w};
#pragma unroll
                for (int i = 0; i < 4; ++i) {
                    float p = pv[i][jj];
#pragma unroll
                    for (int c2 = 0; c2 < 8; ++c2) o[i][c2] += p * vv[c2];
                }
            }
        }
    }

#pragma unroll
    for (int i = 0; i < 4; ++i) {
        float inv = 1.f / l_r[i];
        float* orow = g_attn + (size_t)(b * L_ + l0 + gq * 4 + i) * NQ_
                      + h * HD_ + cc * 8;
        *reinterpret_cast<float4*>(orow) =
            make_float4(o[i][0] * inv, o[i][1] * inv, o[i][2] * inv, o[i][3] * inv);
        *reinterpret_cast<float4*>(orow + 4) =
            make_float4(o[i][4] * inv, o[i][5] * inv, o[i][6] * inv, o[i][7] * inv);
    }
}

// ---------------------------------------------------------------------------
// Launch
// ---------------------------------------------------------------------------
extern "C" void kernel_launch(void* const* d_in, const int* in_sizes, int n_in,
                              void* d_out, int out_size)
{
    const float* x    = (const float*)d_in[0];
    const float* wq   = (const float*)d_in[1];
    const float* wk   = (const float*)d_in[2];
    const float* wv   = (const float*)d_in[3];
    const float* wo   = (const float*)d_in[4];
    const float* cosp = (const float*)d_in[5];
    const float* sinp = (const float*)d_in[6];
    // d_in[7] = mask: exactly causal -1e9; handled analytically in-kernel.
    float* out = (float*)d_out;

    float *qp, *kp, *vp, *ap;
    cudaGetSymbolAddress((void**)&qp, g_q);
    cudaGetSymbolAddress((void**)&kp, g_k);
    cudaGetSymbolAddress((void**)&vp, g_v);
    cudaGetSymbolAddress((void**)&ap, g_attn);

    __nv_bfloat16 *xh, *xl, *wqh, *wql, *wkh, *wkl, *wvh, *wvl, *woh, *wol, *ah, *al;
    cudaGetSymbolAddress((void**)&xh,  g_xh);  cudaGetSymbolAddress((void**)&xl,  g_xl);
    cudaGetSymbolAddress((void**)&wqh, g_wqh); cudaGetSymbolAddress((void**)&wql, g_wql);
    cudaGetSymbolAddress((void**)&wkh, g_wkh); cudaGetSymbolAddress((void**)&wkl, g_wkl);
    cudaGetSymbolAddress((void**)&wvh, g_wvh); cudaGetSymbolAddress((void**)&wvl, g_wvl);
    cudaGetSymbolAddress((void**)&woh, g_woh); cudaGetSymbolAddress((void**)&wol, g_wol);
    cudaGetSymbolAddress((void**)&ah,  g_ah);  cudaGetSymbolAddress((void**)&al,  g_al);

    cudaFuncSetAttribute(gemm_mma, cudaFuncAttributeMaxDynamicSharedMemorySize, GSMEM);
    cudaFuncSetAttribute(attn_kernel, cudaFuncAttributeMaxDynamicSharedMemorySize, ATTN_SMEM);

    const int nx4  = M_ * D_ / 4;
    const int nkv4 = NKV_ * D_ / 4;
    split_kernel<<<(nx4 + 255) / 256, 256>>>(x,  xh,  xl,  nx4);
    split_kernel<<<(nx4 + 255) / 256, 256>>>(wq, wqh, wql, nx4);
    split_kernel<<<(nkv4 + 255) / 256, 256>>>(wk, wkh, wkl, nkv4);
    split_kernel<<<(nkv4 + 255) / 256, 256>>>(wv, wvh, wvl, nkv4);
    split_kernel<<<(nx4 + 255) / 256, 256>>>(wo, woh, wol, nx4);

    gemm_mma<<<dim3(NQ_ / 128,  M_ / 128), 256, GSMEM>>>(xh, xl, wqh, wql, qp, M_, NQ_,  D_);
    gemm_mma<<<dim3(NKV_ / 128, M_ / 128), 256, GSMEM>>>(xh, xl, wkh, wkl, kp, M_, NKV_, D_);
    gemm_mma<<<dim3(NKV_ / 128, M_ / 128), 256, GSMEM>>>(xh, xl, wvh, wvl, vp, M_, NKV_, D_);

    int tq = M_ * H_ * 64;
    rope_kernel<<<(tq + 255) / 256, 256>>>(qp, cosp, sinp, H_, tq);
    int tk = M_ * HKV_ * 64;
    rope_kernel<<<(tk + 255) / 256, 256>>>(kp, cosp, sinp, HKV_, tk);

    attn_kernel<<<dim3(L_ / 64, B_ * H_), 256, ATTN_SMEM>>>();

    split_kernel<<<(nx4 + 255) / 256, 256>>>(ap, ah, al, nx4);
    gemm_mma<<<dim3(D_ / 128, M_ / 128), 256, GSMEM>>>(ah, al, woh, wol, out, M_, D_, D_);
}

// round 4
// speedup vs baseline: 3.0173x; 1.5606x over previous
#include <cuda_runtime.h>
#include <cuda_bf16.h>
#include <math.h>
#include <stdint.h>

#define B_   2
#define L_   2048
#define D_   4096
#define H_   32
#define HKV_ 8
#define HD_  128
#define M_   (B_ * L_)      // 4096 rows
#define NQ_  (H_ * HD_)     // 4096
#define NKV_ (HKV_ * HD_)   // 1024

// ---------------------------------------------------------------------------
// Scratch (device globals; no allocation allowed)
// ---------------------------------------------------------------------------
__device__ float g_q[M_ * NQ_];
__device__ float g_k[M_ * NKV_];
__device__ float g_v[M_ * NKV_];

__device__ __nv_bfloat16 g_xh[M_ * D_],    g_xl[M_ * D_];
__device__ __nv_bfloat16 g_wqh[D_ * D_],   g_wql[D_ * D_];
__device__ __nv_bfloat16 g_wkh[NKV_ * D_], g_wkl[NKV_ * D_];
__device__ __nv_bfloat16 g_wvh[NKV_ * D_], g_wvl[NKV_ * D_];
__device__ __nv_bfloat16 g_woh[D_ * D_],   g_wol[D_ * D_];
__device__ __nv_bfloat16 g_ah[M_ * NQ_],   g_al[M_ * NQ_];

__device__ __nv_bfloat16 g_qh[M_ * NQ_],   g_ql[M_ * NQ_];
__device__ __nv_bfloat16 g_kh[M_ * NKV_],  g_kl[M_ * NKV_];
__device__ __nv_bfloat16 g_vh[M_ * NKV_],  g_vl[M_ * NKV_];

// ---------------------------------------------------------------------------
// Portable tensor-core primitives (plain sm_103 target)
// ---------------------------------------------------------------------------
__device__ __forceinline__ uint32_t s2u(const void* p)
{
    uint32_t a;
    asm("{ .reg .u64 t; cvta.to.shared.u64 t, %1; cvt.u32.u64 %0, t; }"
        : "=r"(a) : "l"(p));
    return a;
}

__device__ __forceinline__ void cpa16(uint32_t s, const void* g)
{
    asm volatile("cp.async.cg.shared.global [%0], [%1], 16;"
                 :: "r"(s), "l"(g) : "memory");
}
#define CP_COMMIT() asm volatile("cp.async.commit_group;" ::: "memory")
#define CP_WAIT2()  asm volatile("cp.async.wait_group 2;" ::: "memory")
#define CP_WAIT1()  asm volatile("cp.async.wait_group 1;" ::: "memory")

__device__ __forceinline__ void ldm4(uint32_t* r, uint32_t addr)
{
    asm volatile("ldmatrix.sync.aligned.m8n8.x4.shared.b16 {%0,%1,%2,%3}, [%4];"
                 : "=r"(r[0]), "=r"(r[1]), "=r"(r[2]), "=r"(r[3]) : "r"(addr));
}

__device__ __forceinline__ void ldm4t(uint32_t* r, uint32_t addr)
{
    asm volatile("ldmatrix.sync.aligned.m8n8.x4.trans.shared.b16 {%0,%1,%2,%3}, [%4];"
                 : "=r"(r[0]), "=r"(r[1]), "=r"(r[2]), "=r"(r[3]) : "r"(addr));
}

__device__ __forceinline__ void mma16816(float* c, const uint32_t* a, const uint32_t* b)
{
    asm volatile(
        "mma.sync.aligned.m16n8k16.row.col.f32.bf16.bf16.f32 "
        "{%0,%1,%2,%3}, {%4,%5,%6,%7}, {%8,%9}, {%0,%1,%2,%3};"
        : "+f"(c[0]), "+f"(c[1]), "+f"(c[2]), "+f"(c[3])
        : "r"(a[0]), "r"(a[1]), "r"(a[2]), "r"(a[3]), "r"(b[0]), "r"(b[1]));
}

// split two fp32 into hi/lo bf16x2 packs (low half = first arg)
__device__ __forceinline__ void split2(float x, float y, uint32_t& hi, uint32_t& lo)
{
    __nv_bfloat16 hx = __float2bfloat16(x);
    __nv_bfloat16 hy = __float2bfloat16(y);
    float lx = x - __bfloat162float(hx);
    float ly = y - __bfloat162float(hy);
    __nv_bfloat162 hp = __halves2bfloat162(hx, hy);
    __nv_bfloat162 lp = __halves2bfloat162(__float2bfloat16(lx), __float2bfloat16(ly));
    hi = *reinterpret_cast<uint32_t*>(&hp);
    lo = *reinterpret_cast<uint32_t*>(&lp);
}

// ---------------------------------------------------------------------------
// HMMA GEMM (unchanged from round 3): C[M,N] = A[M,K]*B[N,K]^T, split-bf16.
// ---------------------------------------------------------------------------
#define STAGE_BYTES 32768
#define OFF_AH 0
#define OFF_AL 8192
#define OFF_BH 16384
#define OFF_BL 24576
#define GSMEM  (4 * STAGE_BYTES)

__global__ __launch_bounds__(256, 1)
void gemm_mma(const __nv_bfloat16* __restrict__ Ah, const __nv_bfloat16* __restrict__ Al,
              const __nv_bfloat16* __restrict__ Bh, const __nv_bfloat16* __restrict__ Bl,
              float* __restrict__ C, int M, int N, int K)
{
    extern __shared__ char smem[];
    const uint32_t sb0 = s2u(smem);
    const int tid  = threadIdx.x;
    const int lane = tid & 31;
    const int wid  = tid >> 5;
    const int warp_m = (wid >> 2) * 64;
    const int warp_n = (wid & 3) * 32;
    const int m0 = blockIdx.y << 7;
    const int n0 = blockIdx.x << 7;

    int ld_row[2], ld_c[2];
    uint32_t ld_soff[2];
#pragma unroll
    for (int i = 0; i < 2; ++i) {
        int idx = tid + i * 256;
        ld_row[i] = idx >> 2;
        ld_c[i]   = idx & 3;
        ld_soff[i] = (uint32_t)(ld_row[i] * 64 +
                     ((ld_c[i] ^ ((ld_row[i] >> 1) & 3)) * 16));
    }

    float acc[4][4][4];
#pragma unroll
    for (int mt = 0; mt < 4; ++mt)
#pragma unroll
        for (int nt = 0; nt < 4; ++nt)
#pragma unroll
            for (int e = 0; e < 4; ++e) acc[mt][nt][e] = 0.f;

    const int NKI = K >> 5;

    const int a_r8 = ((lane >> 3) & 1) * 8 + (lane & 7);
    const int a_cs = lane >> 4;
    const int b_r8 = ((lane >> 4) & 1) * 8 + (lane & 7);
    const int b_cs = (lane >> 3) & 1;

    auto load_stage = [&](int stage, int kc) {
        uint32_t sb = sb0 + stage * STAGE_BYTES;
#pragma unroll
        for (int i = 0; i < 2; ++i) {
            size_t ga = (size_t)(m0 + ld_row[i]) * K + kc + ld_c[i] * 8;
            size_t gb = (size_t)(n0 + ld_row[i]) * K + kc + ld_c[i] * 8;
            cpa16(sb + OFF_AH + ld_soff[i], Ah + ga);
            cpa16(sb + OFF_AL + ld_soff[i], Al + ga);
            cpa16(sb + OFF_BH + ld_soff[i], Bh + gb);
            cpa16(sb + OFF_BL + ld_soff[i], Bl + gb);
        }
    };

#pragma unroll
    for (int s = 0; s < 3; ++s) { load_stage(s, s * 32); CP_COMMIT(); }

    for (int it = 0; it < NKI; ++it) {
        CP_WAIT2();
        __syncthreads();
        if (it + 3 < NKI) load_stage((it + 3) & 3, (it + 3) * 32);
        CP_COMMIT();

        const uint32_t sb = sb0 + (it & 3) * STAGE_BYTES;
#pragma unroll
        for (int j = 0; j < 2; ++j) {
            uint32_t ah[4][4], al[4][4];
#pragma unroll
            for (int mt = 0; mt < 4; ++mt) {
                int row = warp_m + mt * 16 + a_r8;
                int chunk = j * 2 + a_cs;
                uint32_t off = (uint32_t)(row * 64 + ((chunk ^ ((row >> 1) & 3)) * 16));
                ldm4(ah[mt], sb + OFF_AH + off);
                ldm4(al[mt], sb + OFF_AL + off);
            }
            uint32_t bh[4][2], bl[4][2];
#pragma unroll
            for (int np = 0; np < 2; ++np) {
                int row = warp_n + np * 16 + b_r8;
                int chunk = j * 2 + b_cs;
                uint32_t off = (uint32_t)(row * 64 + ((chunk ^ ((row >> 1) & 3)) * 16));
                uint32_t r[4];
                ldm4(r, sb + OFF_BH + off);
                bh[np * 2][0] = r[0]; bh[np * 2][1] = r[1];
                bh[np * 2 + 1][0] = r[2]; bh[np * 2 + 1][1] = r[3];
                ldm4(r, sb + OFF_BL + off);
                bl[np * 2][0] = r[0]; bl[np * 2][1] = r[1];
                bl[np * 2 + 1][0] = r[2]; bl[np * 2 + 1][1] = r[3];
            }
#pragma unroll
            for (int mt = 0; mt < 4; ++mt)
#pragma unroll
                for (int nt = 0; nt < 4; ++nt) {
                    mma16816(acc[mt][nt], ah[mt], bh[nt]);
                    mma16816(acc[mt][nt], ah[mt], bl[nt]);
                    mma16816(acc[mt][nt], al[mt], bh[nt]);
                }
        }
    }

    const int r0 = lane >> 2;
    const int cp = (lane & 3) * 2;
#pragma unroll
    for (int mt = 0; mt < 4; ++mt) {
#pragma unroll
        for (int nt = 0; nt < 4; ++nt) {
            int row = m0 + warp_m + mt * 16 + r0;
            int col = n0 + warp_n + nt * 8 + cp;
            *reinterpret_cast<float2*>(C + (size_t)row * N + col) =
                make_float2(acc[mt][nt][0], acc[mt][nt][1]);
            *reinterpret_cast<float2*>(C + (size_t)(row + 8) * N + col) =
                make_float2(acc[mt][nt][2], acc[mt][nt][3]);
        }
    }
}

// ---------------------------------------------------------------------------
// fp32 -> bf16 hi/lo split
// ---------------------------------------------------------------------------
__global__ void split_kernel(const float* __restrict__ s,
                             __nv_bfloat16* __restrict__ hi,
                             __nv_bfloat16* __restrict__ lo, int n4)
{
    int i = blockIdx.x * blockDim.x + threadIdx.x;
    if (i >= n4) return;
    float4 v = reinterpret_cast<const float4*>(s)[i];
    float f[4] = {v.x, v.y, v.z, v.w};
    __nv_bfloat16 h[4], l[4];
#pragma unroll
    for (int j = 0; j < 4; ++j) {
        h[j] = __float2bfloat16(f[j]);
        l[j] = __float2bfloat16(f[j] - __bfloat162float(h[j]));
    }
    reinterpret_cast<__nv_bfloat162*>(hi)[2 * i]     = __halves2bfloat162(h[0], h[1]);
    reinterpret_cast<__nv_bfloat162*>(hi)[2 * i + 1] = __halves2bfloat162(h[2], h[3]);
    reinterpret_cast<__nv_bfloat162*>(lo)[2 * i]     = __halves2bfloat162(l[0], l[1]);
    reinterpret_cast<__nv_bfloat162*>(lo)[2 * i + 1] = __halves2bfloat162(l[2], l[3]);
}

// ---------------------------------------------------------------------------
// RoPE fused with hi/lo bf16 split (scale folded in for Q)
// ---------------------------------------------------------------------------
__global__ void rope_split(const float* __restrict__ t,
                           __nv_bfloat16* __restrict__ hi, __nv_bfloat16* __restrict__ lo,
                           const float* __restrict__ cosp, const float* __restrict__ sinp,
                           int nh, float scale, int total)
{
    int idx = blockIdx.x * blockDim.x + threadIdx.x;
    if (idx >= total) return;
    int p = idx & 63;
    int h = (idx >> 6) % nh;
    int m = idx / (64 * nh);
    int l = m & (L_ - 1);
    float c = cosp[l * 64 + p];
    float s = sinp[l * 64 + p];
    size_t off = (size_t)m * (nh * HD_) + h * HD_ + (p << 1);
    float tr = t[off], ti = t[off + 1];
    float orr = (tr * c - ti * s) * scale;
    float oii = (tr * s + ti * c) * scale;
    __nv_bfloat16 hr = __float2bfloat16(orr);
    __nv_bfloat16 hic = __float2bfloat16(oii);
    float lr = orr - __bfloat162float(hr);
    float li = oii - __bfloat162float(hic);
    *reinterpret_cast<__nv_bfloat162*>(hi + off) = __halves2bfloat162(hr, hic);
    *reinterpret_cast<__nv_bfloat162*>(lo + off) =
        __halves2bfloat162(__float2bfloat16(lr), __float2bfloat16(li));
}

// ---------------------------------------------------------------------------
// HMMA flash attention (causal, GQA 4:1). Block = 128 queries x (b,h).
// 8 warps x 16 rows. K/V double-buffered 64-key tiles. Split-bf16 both mm.
// Smem rows: 128 bf16 = 256B = 16 chunks; swizzle chunk ^= (row & 7).
// ---------------------------------------------------------------------------
#define A_QH   0
#define A_QL   32768
#define A_KV   65536
#define KV_STG 65536
#define KV_KH  0
#define KV_KL  16384
#define KV_VH  32768
#define KV_VL  49152
#define AT_SMEM (A_KV + 2 * KV_STG)    // 196608

__device__ __forceinline__ uint32_t so_(int row, int chunk)
{
    return (uint32_t)(row * 256 + (((chunk) ^ (row & 7)) << 4));
}

__global__ __launch_bounds__(256, 1)
void attn_mma()
{
    extern __shared__ char smem[];
    const uint32_t sb = s2u(smem);
    const int tid = threadIdx.x, lane = tid & 31, w = tid >> 5;
    const int qt = blockIdx.x, bh = blockIdx.y;
    const int b = bh >> 5, h = bh & 31, hkv = h >> 2;
    const int q0 = qt << 7;
    const int nkt = 2 * qt + 2;

    // ---- Q tile load (hi+lo), cp.async group 0 ----
#pragma unroll
    for (int i = 0; i < 8; ++i) {
        int idx = tid + i * 256;          // 0..2047
        int row = idx >> 4, c = idx & 15;
        size_t go = (size_t)(b * L_ + q0 + row) * NQ_ + h * HD_ + c * 8;
        cpa16(sb + A_QH + so_(row, c), g_qh + go);
        cpa16(sb + A_QL + so_(row, c), g_ql + go);
    }
    CP_COMMIT();

    auto load_kv = [&](int stage, int k0) {
        uint32_t kb = sb + A_KV + stage * KV_STG;
#pragma unroll
        for (int i = 0; i < 4; ++i) {
            int idx = tid + i * 256;      // 0..1023
            int row = idx >> 4, c = idx & 15;
            size_t go = (size_t)(b * L_ + k0 + row) * NKV_ + hkv * HD_ + c * 8;
            uint32_t s = so_(row, c);
            cpa16(kb + KV_KH + s, g_kh + go);
            cpa16(kb + KV_KL + s, g_kl + go);
            cpa16(kb + KV_VH + s, g_vh + go);
            cpa16(kb + KV_VL + s, g_vl + go);
        }
    };

    load_kv(0, 0);
    CP_COMMIT();
    CP_WAIT1();          // Q done (stage0 may still fly)
    __syncthreads();

    float m0 = -INFINITY, m1 = -INFINITY, l0 = 0.f, l1 = 0.f;
    float o[16][4];
#pragma unroll
    for (int n = 0; n < 16; ++n)
#pragma unroll
        for (int e = 0; e < 4; ++e) o[n][e] = 0.f;

    const int t4 = lane >> 3;             // ldmatrix lane group 0..3
    const int r8 = lane & 7;

    for (int kt = 0; kt < nkt; ++kt) {
        const int k0 = kt * 64;
        const int stage = kt & 1;
        if (kt + 1 < nkt) load_kv(stage ^ 1, (kt + 1) * 64);
        CP_COMMIT();
        CP_WAIT1();
        __syncthreads();

        const uint32_t kb = sb + A_KV + stage * KV_STG;

        // ---- S = Q K^T (3 products) ----
        float s[8][4];
#pragma unroll
        for (int j = 0; j < 8; ++j)
#pragma unroll
            for (int e = 0; e < 4; ++e) s[j][e] = 0.f;

#pragma unroll
        for (int ks = 0; ks < 8; ++ks) {
            uint32_t qh[4], ql[4];
            {
                int row = w * 16 + (t4 & 1) * 8 + r8;
                int ch  = ks * 2 + (t4 >> 1);
                ldm4(qh, sb + A_QH + so_(row, ch));
                ldm4(ql, sb + A_QL + so_(row, ch));
            }
            uint32_t kh[8][2], klo[8][2];
#pragma unroll
            for (int jp = 0; jp < 4; ++jp) {
                int row = (jp * 2 + (t4 >> 1)) * 8 + r8;
                int ch  = ks * 2 + (t4 & 1);
                uint32_t r[4];
                ldm4(r, kb + KV_KH + so_(row, ch));
                kh[2 * jp][0] = r[0]; kh[2 * jp][1] = r[1];
                kh[2 * jp + 1][0] = r[2]; kh[2 * jp + 1][1] = r[3];
                ldm4(r, kb + KV_KL + so_(row, ch));
                klo[2 * jp][0] = r[0]; klo[2 * jp][1] = r[1];
                klo[2 * jp + 1][0] = r[2]; klo[2 * jp + 1][1] = r[3];
            }
#pragma unroll
            for (int j = 0; j < 8; ++j) {
                mma16816(s[j], qh, kh[j]);
                mma16816(s[j], qh, klo[j]);
                mma16816(s[j], ql, kh[j]);
            }
        }

        // ---- causal mask (only tiles touching/above diagonal) ----
        if (kt >= 2 * qt) {
            int qrow = q0 + w * 16 + (lane >> 2);
#pragma unroll
            for (int j = 0; j < 8; ++j) {
                int kc = k0 + j * 8 + (lane & 3) * 2;
                if (kc     > qrow)     s[j][0] = -1e30f;
                if (kc + 1 > qrow)     s[j][1] = -1e30f;
                if (kc     > qrow + 8) s[j][2] = -1e30f;
                if (kc + 1 > qrow + 8) s[j][3] = -1e30f;
            }
        }

        // ---- online softmax ----
        float rm0 = -INFINITY, rm1 = -INFINITY;
#pragma unroll
        for (int j = 0; j < 8; ++j) {
            rm0 = fmaxf(rm0, fmaxf(s[j][0], s[j][1]));
            rm1 = fmaxf(rm1, fmaxf(s[j][2], s[j][3]));
        }
        rm0 = fmaxf(rm0, __shfl_xor_sync(0xffffffffu, rm0, 1));
        rm0 = fmaxf(rm0, __shfl_xor_sync(0xffffffffu, rm0, 2));
        rm1 = fmaxf(rm1, __shfl_xor_sync(0xffffffffu, rm1, 1));
        rm1 = fmaxf(rm1, __shfl_xor_sync(0xffffffffu, rm1, 2));
        float mn0 = fmaxf(m0, rm0), mn1 = fmaxf(m1, rm1);
        float a0 = __expf(m0 - mn0), a1 = __expf(m1 - mn1);
        float rs0 = 0.f, rs1 = 0.f;
#pragma unroll
        for (int j = 0; j < 8; ++j) {
            s[j][0] = __expf(s[j][0] - mn0);
            s[j][1] = __expf(s[j][1] - mn0);
            s[j][2] = __expf(s[j][2] - mn1);
            s[j][3] = __expf(s[j][3] - mn1);
            rs0 += s[j][0] + s[j][1];
            rs1 += s[j][2] + s[j][3];
        }
        rs0 += __shfl_xor_sync(0xffffffffu, rs0, 1);
        rs0 += __shfl_xor_sync(0xffffffffu, rs0, 2);
        rs1 += __shfl_xor_sync(0xffffffffu, rs1, 1);
        rs1 += __shfl_xor_sync(0xffffffffu, rs1, 2);
        l0 = l0 * a0 + rs0; l1 = l1 * a1 + rs1;
        m0 = mn0; m1 = mn1;
#pragma unroll
        for (int n = 0; n < 16; ++n) {
            o[n][0] *= a0; o[n][1] *= a0;
            o[n][2] *= a1; o[n][3] *= a1;
        }

        // ---- O += P V (3 products), V via ldmatrix.trans ----
#pragma unroll
        for (int ks = 0; ks < 4; ++ks) {
            uint32_t ph[4], pl[4];
            split2(s[2 * ks][0],     s[2 * ks][1],     ph[0], pl[0]);
            split2(s[2 * ks][2],     s[2 * ks][3],     ph[1], pl[1]);
            split2(s[2 * ks + 1][0], s[2 * ks + 1][1], ph[2], pl[2]);
            split2(s[2 * ks + 1][2], s[2 * ks + 1][3], ph[3], pl[3]);
#pragma unroll
            for (int np = 0; np < 8; ++np) {
                int n = np * 2;
                int row = ks * 16 + (t4 & 1) * 8 + r8;
                int ch  = n + (t4 >> 1);
                uint32_t rh[4], rl[4];
                ldm4t(rh, kb + KV_VH + so_(row, ch));
                ldm4t(rl, kb + KV_VL + so_(row, ch));
                mma16816(o[n], ph, rh);
                mma16816(o[n], ph, rl);
                mma16816(o[n], pl, rh);
                mma16816(o[n + 1], ph, rh + 2);
                mma16816(o[n + 1], ph, rl + 2);
                mma16816(o[n + 1], pl, rh + 2);
            }
        }
        __syncthreads();
    }

    // ---- epilogue: O/l, split hi/lo, store ----
    float i0 = 1.f / l0, i1 = 1.f / l1;
    int row0 = b * L_ + q0 + w * 16 + (lane >> 2);
    int colb = h * HD_ + (lane & 3) * 2;
#pragma unroll
    for (int n = 0; n < 16; ++n) {
        uint32_t h01, l01, h23, l23;
        split2(o[n][0] * i0, o[n][1] * i0, h01, l01);
        split2(o[n][2] * i1, o[n][3] * i1, h23, l23);
        size_t off0 = (size_t)row0 * NQ_ + colb + n * 8;
        size_t off1 = off0 + (size_t)8 * NQ_;
        *reinterpret_cast<uint32_t*>(g_ah + off0) = h01;
        *reinterpret_cast<uint32_t*>(g_al + off0) = l01;
        *reinterpret_cast<uint32_t*>(g_ah + off1) = h23;
        *reinterpret_cast<uint32_t*>(g_al + off1) = l23;
    }
}

// ---------------------------------------------------------------------------
// Launch
// ---------------------------------------------------------------------------
extern "C" void kernel_launch(void* const* d_in, const int* in_sizes, int n_in,
                              void* d_out, int out_size)
{
    const float* x    = (const float*)d_in[0];
    const float* wq   = (const float*)d_in[1];
    const float* wk   = (const float*)d_in[2];
    const float* wv   = (const float*)d_in[3];
    const float* wo   = (const float*)d_in[4];
    const float* cosp = (const float*)d_in[5];
    const float* sinp = (const float*)d_in[6];
    // d_in[7] = mask: exactly causal -1e9; handled analytically in-kernel.
    float* out = (float*)d_out;

    float *qp, *kp, *vp;
    cudaGetSymbolAddress((void**)&qp, g_q);
    cudaGetSymbolAddress((void**)&kp, g_k);
    cudaGetSymbolAddress((void**)&vp, g_v);

    __nv_bfloat16 *xh, *xl, *wqh, *wql, *wkh, *wkl, *wvh, *wvl, *woh, *wol,
                  *ah, *al, *qh, *ql, *kh, *kl, *vh, *vl;
    cudaGetSymbolAddress((void**)&xh,  g_xh);  cudaGetSymbolAddress((void**)&xl,  g_xl);
    cudaGetSymbolAddress((void**)&wqh, g_wqh); cudaGetSymbolAddress((void**)&wql, g_wql);
    cudaGetSymbolAddress((void**)&wkh, g_wkh); cudaGetSymbolAddress((void**)&wkl, g_wkl);
    cudaGetSymbolAddress((void**)&wvh, g_wvh); cudaGetSymbolAddress((void**)&wvl, g_wvl);
    cudaGetSymbolAddress((void**)&woh, g_woh); cudaGetSymbolAddress((void**)&wol, g_wol);
    cudaGetSymbolAddress((void**)&ah,  g_ah);  cudaGetSymbolAddress((void**)&al,  g_al);
    cudaGetSymbolAddress((void**)&qh,  g_qh);  cudaGetSymbolAddress((void**)&ql,  g_ql);
    cudaGetSymbolAddress((void**)&kh,  g_kh);  cudaGetSymbolAddress((void**)&kl,  g_kl);
    cudaGetSymbolAddress((void**)&vh,  g_vh);  cudaGetSymbolAddress((void**)&vl,  g_vl);

    cudaFuncSetAttribute(gemm_mma, cudaFuncAttributeMaxDynamicSharedMemorySize, GSMEM);
    cudaFuncSetAttribute(attn_mma, cudaFuncAttributeMaxDynamicSharedMemorySize, AT_SMEM);

    const int nx4  = M_ * D_ / 4;
    const int nkv4 = NKV_ * D_ / 4;
    split_kernel<<<(nx4 + 255) / 256, 256>>>(x,  xh,  xl,  nx4);
    split_kernel<<<(nx4 + 255) / 256, 256>>>(wq, wqh, wql, nx4);
    split_kernel<<<(nkv4 + 255) / 256, 256>>>(wk, wkh, wkl, nkv4);
    split_kernel<<<(nkv4 + 255) / 256, 256>>>(wv, wvh, wvl, nkv4);
    split_kernel<<<(nx4 + 255) / 256, 256>>>(wo, woh, wol, nx4);

    gemm_mma<<<dim3(NQ_ / 128,  M_ / 128), 256, GSMEM>>>(xh, xl, wqh, wql, qp, M_, NQ_,  D_);
    gemm_mma<<<dim3(NKV_ / 128, M_ / 128), 256, GSMEM>>>(xh, xl, wkh, wkl, kp, M_, NKV_, D_);
    gemm_mma<<<dim3(NKV_ / 128, M_ / 128), 256, GSMEM>>>(xh, xl, wvh, wvl, vp, M_, NKV_, D_);

    const float qscale = 0.08838834764831845f;   // 1/sqrt(128)
    int tq = M_ * H_ * 64;
    rope_split<<<(tq + 255) / 256, 256>>>(qp, qh, ql, cosp, sinp, H_, qscale, tq);
    int tk = M_ * HKV_ * 64;
    rope_split<<<(tk + 255) / 256, 256>>>(kp, kh, kl, cosp, sinp, HKV_, 1.0f, tk);

    int nv4 = M_ * NKV_ / 4;
    split_kernel<<<(nv4 + 255) / 256, 256>>>(vp, vh, vl, nv4);

    attn_mma<<<dim3(L_ / 128, B_ * H_), 256, AT_SMEM>>>();

    gemm_mma<<<dim3(D_ / 128, M_ / 128), 256, GSMEM>>>(ah, al, woh, wol, out, M_, D_, D_);
}